// round 15
// baseline (speedup 1.0000x reference)
#include <cuda_runtime.h>
#include <cuda_fp16.h>
#include <mma.h>
#include <cstdint>

using namespace nvcuda;

#define B_   1024
#define H_   512
#define E_   256
#define S_   128
#define T_   128
#define V_   128
#define G4   2048
#define NCTA 256                 // 32 j-tiles x 8 b-groups
#define NSTEP (S_ + T_ - 1)      // 255
#define THREADS 256
#define LDH  520                 // smem ld (halves) for resident W rows
#define LDW  72                  // smem ld (halves) for streamed h chunks
#define CHUNKB (128 * LDW * 2)   // 18432 bytes per 64-k chunk
#define W2BYTES (64 * LDH * 2)   // 66560: resident W tile (64 gate-rows)
#define GS2_B  (128 * 68 * 4)    // 34816: gate staging fp32 [128 b][68 j]
#define HO2_B  (128 * 20 * 4)    // 10240: hout fp32 [128 b][20 h]
#define SEQ_SMEM (W2BYTES + GS2_B + HO2_B)            // 111616 -> 2 CTAs/SM
#define FC_SMEM  (128 * LDH * 2 + 2 * 128 * LDW * 2)  // 169984

// ---------------- device scratch ----------------
__device__ __half g_W2[2][32 * 64 * H_];             // reordered whh fp16: [jh][gate*16+r][k]
__device__ float  g_embp[2][(long)V_ * G4];          // emb @ wih^T + bih + bhh (exact fp32)
__device__ __half g_fcw16[V_ * H_];
__device__ float  g_biasfc[16 * V_];
__device__ __half g_hf[2][(long)B_ * H_];            // hidden fp16, double buffered (cross-CTA via L2)
__device__ __half g_hseq[(long)B_ * (T_ - 1) * H_];
__device__ float  g_logits[(long)B_ * (T_ - 1) * V_];
__device__ unsigned g_bar8[8 * 32];                  // per-b-group barrier counters (128B apart)

// fast activations: MUFU-based, rel err ~1e-6 (validated R7-R14)
__device__ __forceinline__ float sigm(float x) {
    return __fdividef(1.f, 1.f + __expf(-x));
}
__device__ __forceinline__ float tanhfast(float x) {
    float s = __fdividef(1.f, 1.f + __expf(-2.f * x));
    return fmaf(2.f, s, -1.f);
}

__device__ __forceinline__ void cpa16(void* dst, const void* src) {
    unsigned d = (unsigned)__cvta_generic_to_shared(dst);
    asm volatile("cp.async.cg.shared.global [%0], [%1], 16;\n" :: "r"(d), "l"(src));
}
#define CPC()  asm volatile("cp.async.commit_group;\n" ::: "memory")
#define CPW(n) asm volatile("cp.async.wait_group %0;\n" :: "n"(n) : "memory")

// copy 64-k chunk ch of this CTA's h tile into smem buffer (all 256 threads, 4 ops each)
#define CPCH(buf, ch)                                                             \
    _Pragma("unroll")                                                             \
    for (int it_ = 0; it_ < 4; it_++) {                                           \
        int i_ = threadIdx.x + it_ * THREADS;                                     \
        int r_ = i_ >> 3, q_ = i_ & 7;                                            \
        cpa16((buf) + r_ * LDW + q_ * 8, hg + (long)(b0 + r_) * H_ + (ch) * 64 + q_ * 8); \
    }

// ---------------- prep A: embproj = emb @ wih^T + bih + bhh (exact fp32) ----------------
__global__ void prep_embproj(const float* __restrict__ emb, const float* __restrict__ wih,
                             const float* __restrict__ bih, const float* __restrict__ bhh,
                             int is_dec)
{
    __shared__ float er[E_];
    int v = blockIdx.x;
    int n = blockIdx.y * 256 + threadIdx.x;
    er[threadIdx.x] = emb[(long)v * E_ + threadIdx.x];
    __syncthreads();
    float s = bih[n] + bhh[n];
    const float* wr = wih + (long)n * E_;
    #pragma unroll 8
    for (int k = 0; k < E_; k++) s += er[k] * wr[k];
    g_embp[is_dec][(long)v * G4 + n] = s;
}

// ---------------- prep B: reorder whh fp16 (32 j-tiles of 16h x 4 gates), fc, h0, bars ---
__global__ void prep2(const float* __restrict__ enc_whh, const float* __restrict__ dec_whh,
                      const float* __restrict__ fc_w,    const float* __restrict__ fc_b)
{
    if (blockIdx.x == 0 && threadIdx.x < 8 * 32) g_bar8[threadIdx.x] = 0u;
    const long NW  = 32L * 64 * H_;
    const long NFC = (long)V_ * H_;
    const long NB  = 16L * V_;
    const long NS  = (long)B_ * H_;
    const long total = 2 * NW + NFC + NB + NS;
    for (long i = (long)blockIdx.x * blockDim.x + threadIdx.x; i < total;
         i += (long)gridDim.x * blockDim.x) {
        long r = i;
        if (r < 2 * NW) {
            int ed = (int)(r / NW);
            long l = r % NW;
            int jh = (int)(l / (64L * H_));
            int rr = (int)((l / H_) % 64);
            int k  = (int)(l % H_);
            int g = rr >> 4, hh = rr & 15;
            long n = (long)g * H_ + jh * 16 + hh;
            const float* whh = ed ? dec_whh : enc_whh;
            g_W2[ed][l] = __float2half(whh[n * H_ + k]);
        } else if (r < 2 * NW + NFC) {
            long l = r - 2 * NW;
            g_fcw16[l] = __float2half(fc_w[l]);
        } else if (r < 2 * NW + NFC + NB) {
            long l = r - 2 * NW - NFC;
            g_biasfc[l] = fc_b[l % V_];
        } else {
            long l = r - 2 * NW - NFC - NB;
            g_hf[0][l] = __float2half(0.f);
        }
    }
}

// ---------------- persistent kernel: all 255 LSTM steps, 2 CTAs per SM ----------------
// CTA (bg, jh): batch rows bg*128..+127, h-dims jh*16..+15 (x4 gates = 64 gate rows).
// 8 warps = 8 batch sub-tiles of 16; NO K-split: every warp streams all 8 64-k chunks
// and holds FULL gate sums in acc[4] (32 regs). 2 chunk buffers, true double buffering:
// copy c+1 issued after iter-c's sync (which proves c-1 readers done) and hides under
// iter-c mma. Balanced all-warp epilogue; c state in per-warp cfr (8 regs).
__global__ __launch_bounds__(THREADS, 2) void seq_kernel(
    const int* __restrict__ src, const int* __restrict__ tgt)
{
    extern __shared__ __align__(16) char smem[];
    __half* Ws  = (__half*)smem;                        // [64 gate-row][LDH k] resident
    __half* hb0 = (__half*)(smem + W2BYTES);            // chunk buffer 0
    __half* hb1 = (__half*)(smem + W2BYTES + CHUNKB);   // chunk buffer 1
    float*  GS   = (float*)(smem + W2BYTES);            // [128 b][68 j] (aliases hb)
    float*  hout = (float*)(smem + W2BYTES + GS2_B);    // [128 b][20 h]
    __shared__ int tok_s[128];

    const int tid  = threadIdx.x;
    const int warp = tid >> 5;          // b-subtile (16 batch rows)
    const int jh   = blockIdx.x & 31;
    const int b0   = (blockIdx.x >> 5) * 128;
    const int btg  = blockIdx.x >> 5;   // barrier group (32 CTAs each)

    // resident encoder W tile (64 rows x 512 k)
    {
        const __half* __restrict__ W = g_W2[0] + (long)jh * 64 * H_;
        for (int i = tid; i < 64 * 64; i += THREADS) {
            int r = i >> 6, q = i & 63;
            cpa16(Ws + r * LDH + q * 8, W + (long)r * H_ + q * 8);
        }
        CPC(); CPW(0);
        __syncthreads();
    }

    // persistent cell state: warp owns 16 h x 16 b
    wmma::fragment<wmma::accumulator, 16, 16, 16, float> cfr;
    wmma::fill_fragment(cfr, 0.f);

    for (int st = 0; st < NSTEP; ++st) {
        const int is_dec = st >= S_;
        const int t   = is_dec ? st - S_ : st;
        const int par = st & 1;
        const int* __restrict__ tok = is_dec ? tgt : src;
        const __half* __restrict__ hg = g_hf[par];

        if (st == S_) {   // swap to decoder weights (CTA-local)
            const __half* __restrict__ W = g_W2[1] + (long)jh * 64 * H_;
            for (int i = tid; i < 64 * 64; i += THREADS) {
                int r = i >> 6, q = i & 63;
                cpa16(Ws + r * LDH + q * 8, W + (long)r * H_ + q * 8);
            }
            CPC(); CPW(0);
            __syncthreads();
        }

        if (tid < 128) tok_s[tid] = tok[(long)(b0 + tid) * 128 + t];

        // prologue: chunk 0 -> buf0
        CPCH(hb0, 0); CPC();

        wmma::fragment<wmma::accumulator, 16, 16, 16, float> acc[4];
        #pragma unroll
        for (int g = 0; g < 4; g++) wmma::fill_fragment(acc[g], 0.f);

        // single-sync, double-buffered mainloop: all warps consume chunk c together
        #pragma unroll 1
        for (int c = 0; c < 8; c++) {
            CPW(0);
            __syncthreads();            // proves all warps done with iter c-1 (buf[(c+1)&1])
            if (c < 7) {
                __half* nb = (c & 1) ? hb0 : hb1;
                CPCH(nb, c + 1);
                CPC();
            }
            const __half* cw = (c & 1) ? hb1 : hb0;
            #pragma unroll
            for (int kk = 0; kk < 4; kk++) {
                wmma::fragment<wmma::matrix_b, 16, 16, 16, half, wmma::col_major> bf;
                wmma::load_matrix_sync(bf, cw + (warp * 16) * LDW + kk * 16, LDW);
                #pragma unroll
                for (int g = 0; g < 4; g++) {
                    wmma::fragment<wmma::matrix_a, 16, 16, 16, half, wmma::row_major> af;
                    wmma::load_matrix_sync(af, Ws + (g * 16) * LDH + c * 64 + kk * 16, LDH);
                    wmma::mma_sync(acc[g], af, bf, acc[g]);
                }
            }
        }
        __syncthreads();   // all warps done reading hb -> GS alias region free

        // -------- epilogue (balanced, all 8 warps; no partials) --------
        // stage embproj (write-only) into GS [128 b][68 j]
        const float* __restrict__ EP = g_embp[is_dec];
        #pragma unroll
        for (int it = 0; it < 8; it++) {
            int i = tid + it * THREADS;          // 2048 total
            int b = i >> 4, f = i & 15;
            int g = f >> 2, q = f & 3;
            const float4 ev = *reinterpret_cast<const float4*>(
                &EP[(long)tok_s[b] * G4 + (long)g * H_ + jh * 16 + q * 4]);
            *reinterpret_cast<float4*>(&GS[b * 68 + g * 16 + q * 4]) = ev;
        }
        __syncthreads();

        // each warp: add embproj frags, cell update (c in registers), stage h
        {
            const int bl = warp * 16;
            wmma::fragment<wmma::accumulator, 16, 16, 16, float> xf, hn;
            #pragma unroll
            for (int g = 0; g < 4; g++) {
                wmma::load_matrix_sync(xf, GS + bl * 68 + g * 16, 68, wmma::mem_col_major);
                #pragma unroll
                for (int e = 0; e < 8; e++) acc[g].x[e] += xf.x[e];
            }
            #pragma unroll
            for (int e = 0; e < 8; e++) {
                float ig = sigm(acc[0].x[e]);
                float fg = sigm(acc[1].x[e]);
                float gg = tanhfast(acc[2].x[e]);
                float og = sigm(acc[3].x[e]);
                float c2 = fg * cfr.x[e] + ig * gg;
                cfr.x[e] = c2;
                hn.x[e] = og * tanhfast(c2);
            }
            wmma::store_matrix_sync(hout + bl * 20, hn, 20, wmma::mem_col_major);
        }
        __syncthreads();

        // all threads: write h (fp16), vectorized (4 halves each, 2 per thread)
        __half* __restrict__ hg2 = g_hf[par ^ 1];
        #pragma unroll
        for (int it = 0; it < 2; it++) {
            int i = tid + it * THREADS;          // 512 total
            int b = i >> 2, q = i & 3;
            float4 hv = *reinterpret_cast<const float4*>(&hout[b * 20 + q * 4]);
            __half2 h2a = __floats2half2_rn(hv.x, hv.y);
            __half2 h2b = __floats2half2_rn(hv.z, hv.w);
            uint2 o = make_uint2(*reinterpret_cast<uint32_t*>(&h2a),
                                 *reinterpret_cast<uint32_t*>(&h2b));
            *reinterpret_cast<uint2*>(&hg2[(long)(b0 + b) * H_ + jh * 16 + q * 4]) = o;
            if (is_dec)
                *reinterpret_cast<uint2*>(
                    &g_hseq[((long)(b0 + b) * (T_ - 1) + t) * H_ + jh * 16 + q * 4]) = o;
        }

        // -------- per-b-group barrier (32 CTAs), tid0-only cumulative fence --------
        if (st + 1 < NSTEP) {
            __syncthreads();
            if (tid == 0) {
                __threadfence();                   // cumulative after syncthreads
                atomicAdd(&g_bar8[btg * 32], 1u);
                const unsigned target = (unsigned)(st + 1) * 32u;
                while (*(volatile unsigned*)&g_bar8[btg * 32] < target) __nanosleep(64);
            }
            __syncthreads();
        }
    }
}

// ---------------- FC head: logits = h_seq @ fc_w^T + fc_b (fp16 in, fp32 acc) ----------
__global__ __launch_bounds__(256, 1) void fc_kernel()
{
    extern __shared__ __align__(16) char smem[];
    __half* bsm = (__half*)smem;
    __half* ab0 = (__half*)(smem + 128 * LDH * 2);
    __half* ab1 = (__half*)(smem + 128 * LDH * 2 + 128 * LDW * 2);

    const int tid = threadIdx.x;
    const int warp = tid >> 5;
    const int wm = warp >> 2;
    const int wn = warp & 3;
    const long m0 = (long)blockIdx.x * 128;

    for (int i = tid; i < 128 * 64; i += 256) {
        int r = i >> 6, q = i & 63;
        cpa16(bsm + r * LDH + q * 8, g_fcw16 + (long)r * H_ + q * 8);
    }
    for (int i = tid; i < 128 * 8; i += 256) {
        int r = i >> 3, q = i & 7;
        cpa16(ab0 + r * LDW + q * 8, g_hseq + (m0 + r) * H_ + q * 8);
    }
    CPC();
    for (int i = tid; i < 128 * 8; i += 256) {
        int r = i >> 3, q = i & 7;
        cpa16(ab1 + r * LDW + q * 8, g_hseq + (m0 + r) * H_ + 64 + q * 8);
    }
    CPC();
    CPW(1);
    __syncthreads();

    wmma::fragment<wmma::accumulator, 16, 16, 16, float> acc[4][2];
    #pragma unroll
    for (int mm = 0; mm < 4; mm++)
        #pragma unroll
        for (int cb = 0; cb < 2; cb++)
            wmma::load_matrix_sync(acc[mm][cb], g_biasfc + wn * 32 + cb * 16, V_, wmma::mem_row_major);

    #pragma unroll 1
    for (int ch = 0; ch < 8; ch++) {
        const __half* ca = (ch & 1) ? ab1 : ab0;
        #pragma unroll
        for (int kk = 0; kk < 4; kk++) {
            wmma::fragment<wmma::matrix_b, 16, 16, 16, half, wmma::col_major> bf[2];
            #pragma unroll
            for (int cb = 0; cb < 2; cb++)
                wmma::load_matrix_sync(bf[cb], bsm + (wn * 32 + cb * 16) * LDH + ch * 64 + kk * 16, LDH);
            #pragma unroll
            for (int mm = 0; mm < 4; mm++) {
                wmma::fragment<wmma::matrix_a, 16, 16, 16, half, wmma::row_major> af;
                wmma::load_matrix_sync(af, ca + (wm * 64 + mm * 16) * LDW + kk * 16, LDW);
                wmma::mma_sync(acc[mm][0], af, bf[0], acc[mm][0]);
                wmma::mma_sync(acc[mm][1], af, bf[1], acc[mm][1]);
            }
        }
        __syncthreads();
        if (ch + 2 < 8) {
            __half* nb = (ch & 1) ? ab1 : ab0;
            for (int i = tid; i < 128 * 8; i += 256) {
                int r = i >> 3, q = i & 7;
                cpa16(nb + r * LDW + q * 8, g_hseq + (m0 + r) * H_ + (ch + 2) * 64 + q * 8);
            }
            CPC();
        }
        if (ch + 1 < 8) {
            if (ch + 2 < 8) { CPW(1); } else { CPW(0); }
            __syncthreads();
        }
    }

    #pragma unroll
    for (int mm = 0; mm < 4; mm++)
        #pragma unroll
        for (int cb = 0; cb < 2; cb++)
            wmma::store_matrix_sync(g_logits + (m0 + wm * 64 + mm * 16) * V_ + wn * 32 + cb * 16,
                                    acc[mm][cb], V_, wmma::mem_row_major);
}

// ---------------- scatter logits into (B, T, V) with zero row at t=0 ----------------
__global__ void out_kernel(float* __restrict__ out)
{
    const long n4 = (long)B_ * T_ * V_ / 4;
    for (long i = (long)blockIdx.x * blockDim.x + threadIdx.x; i < n4;
         i += (long)gridDim.x * blockDim.x) {
        long e = i * 4;
        int  v  = (int)(e % V_);
        long bt = e / V_;
        int  tt = (int)(bt % T_);
        long b  = bt / T_;
        float4 val;
        if (tt == 0) val = make_float4(0.f, 0.f, 0.f, 0.f);
        else val = *reinterpret_cast<const float4*>(
                       &g_logits[(b * (T_ - 1) + (tt - 1)) * V_ + v]);
        reinterpret_cast<float4*>(out)[i] = val;
    }
}

// ---------------- launch ----------------
extern "C" void kernel_launch(void* const* d_in, const int* in_sizes, int n_in,
                              void* d_out, int out_size)
{
    (void)in_sizes; (void)n_in; (void)out_size;
    const int*   src      = (const int*)  d_in[0];
    const int*   target   = (const int*)  d_in[1];
    const float* emb      = (const float*)d_in[2];
    const float* dec_emb  = (const float*)d_in[3];
    const float* enc_wih  = (const float*)d_in[4];
    const float* enc_whh  = (const float*)d_in[5];
    const float* enc_bih  = (const float*)d_in[6];
    const float* enc_bhh  = (const float*)d_in[7];
    const float* dec_wih  = (const float*)d_in[8];
    const float* dec_whh  = (const float*)d_in[9];
    const float* dec_bih  = (const float*)d_in[10];
    const float* dec_bhh  = (const float*)d_in[11];
    const float* fc_w     = (const float*)d_in[12];
    const float* fc_b     = (const float*)d_in[13];
    float* out = (float*)d_out;

    cudaFuncSetAttribute(seq_kernel, cudaFuncAttributeMaxDynamicSharedMemorySize, SEQ_SMEM);
    cudaFuncSetAttribute(fc_kernel,  cudaFuncAttributeMaxDynamicSharedMemorySize, FC_SMEM);

    prep_embproj<<<dim3(V_, G4 / 256), 256>>>(emb,     enc_wih, enc_bih, enc_bhh, 0);
    prep_embproj<<<dim3(V_, G4 / 256), 256>>>(dec_emb, dec_wih, dec_bih, dec_bhh, 1);
    prep2<<<2048, 256>>>(enc_whh, dec_whh, fc_w, fc_b);

    seq_kernel<<<NCTA, THREADS, SEQ_SMEM>>>(src, target);

    fc_kernel<<<(B_ * (T_ - 1)) / 128, 256, FC_SMEM>>>();
    out_kernel<<<2048, 256>>>(out);
}

// round 16
// speedup vs baseline: 1.5017x; 1.5017x over previous
#include <cuda_runtime.h>
#include <cuda_fp16.h>
#include <mma.h>
#include <cstdint>

using namespace nvcuda;

#define B_   1024
#define H_   512
#define E_   256
#define S_   128
#define T_   128
#define V_   128
#define G4   2048
#define NCTA 256                 // 32 j-tiles x 8 b-groups
#define NSTEP (S_ + T_ - 1)      // 255
#define THREADS 256
#define LDH  520                 // smem ld (halves) for resident W rows
#define LDW  72                  // smem ld (halves) for streamed h chunks
#define CHUNKB (128 * LDW * 2)   // 18432 bytes per 64-k chunk
#define W2BYTES (64 * LDH * 2)   // 66560: resident W tile (64 gate-rows)
#define GS2_B  (128 * 68 * 4)    // 34816: gate staging fp32 [128 b][68 j]
#define HO2_B  (128 * 20 * 4)    // 10240: hout fp32 [128 b][20 h]
#define SEQ_SMEM (W2BYTES + GS2_B + HO2_B)            // 111616 -> 2 CTAs/SM
#define FC_SMEM  (128 * LDH * 2 + 2 * 128 * LDW * 2)  // 169984

// ---------------- device scratch ----------------
__device__ __half g_W2[2][32 * 64 * H_];             // reordered whh fp16: [jh][gate*16+r][k]
__device__ float  g_embp[2][(long)V_ * G4];          // emb @ wih^T + bih + bhh (exact fp32)
__device__ __half g_fcw16[V_ * H_];
__device__ float  g_biasfc[16 * V_];
__device__ __half g_hf[2][(long)B_ * H_];            // hidden fp16, double buffered (cross-CTA via L2)
__device__ __half g_hseq[(long)B_ * (T_ - 1) * H_];
__device__ float  g_logits[(long)B_ * (T_ - 1) * V_];
__device__ unsigned g_bar8[8 * 32];                  // per-b-group barrier counters (128B apart)

// fast activations: MUFU-based, rel err ~1e-6 (validated R7-R15)
__device__ __forceinline__ float sigm(float x) {
    return __fdividef(1.f, 1.f + __expf(-x));
}
__device__ __forceinline__ float tanhfast(float x) {
    float s = __fdividef(1.f, 1.f + __expf(-2.f * x));
    return fmaf(2.f, s, -1.f);
}

__device__ __forceinline__ void cpa16(void* dst, const void* src) {
    unsigned d = (unsigned)__cvta_generic_to_shared(dst);
    asm volatile("cp.async.cg.shared.global [%0], [%1], 16;\n" :: "r"(d), "l"(src));
}
#define CPC()  asm volatile("cp.async.commit_group;\n" ::: "memory")
#define CPW(n) asm volatile("cp.async.wait_group %0;\n" :: "n"(n) : "memory")

// copy 64-k chunk ch of this CTA's h tile into smem buffer (all 256 threads, 4 ops each)
#define CPCH(buf, ch)                                                             \
    _Pragma("unroll")                                                             \
    for (int it_ = 0; it_ < 4; it_++) {                                           \
        int i_ = threadIdx.x + it_ * THREADS;                                     \
        int r_ = i_ >> 3, q_ = i_ & 7;                                            \
        cpa16((buf) + r_ * LDW + q_ * 8, hg + (long)(b0 + r_) * H_ + (ch) * 64 + q_ * 8); \
    }

// ---------------- prep A: embproj = emb @ wih^T + bih + bhh (exact fp32) ----------------
__global__ void prep_embproj(const float* __restrict__ emb, const float* __restrict__ wih,
                             const float* __restrict__ bih, const float* __restrict__ bhh,
                             int is_dec)
{
    __shared__ float er[E_];
    int v = blockIdx.x;
    int n = blockIdx.y * 256 + threadIdx.x;
    er[threadIdx.x] = emb[(long)v * E_ + threadIdx.x];
    __syncthreads();
    float s = bih[n] + bhh[n];
    const float* wr = wih + (long)n * E_;
    #pragma unroll 8
    for (int k = 0; k < E_; k++) s += er[k] * wr[k];
    g_embp[is_dec][(long)v * G4 + n] = s;
}

// ---------------- prep B: reorder whh fp16 (32 j-tiles of 16h x 4 gates), fc, h0, bars ---
__global__ void prep2(const float* __restrict__ enc_whh, const float* __restrict__ dec_whh,
                      const float* __restrict__ fc_w,    const float* __restrict__ fc_b)
{
    if (blockIdx.x == 0 && threadIdx.x < 8 * 32) g_bar8[threadIdx.x] = 0u;
    const long NW  = 32L * 64 * H_;
    const long NFC = (long)V_ * H_;
    const long NB  = 16L * V_;
    const long NS  = (long)B_ * H_;
    const long total = 2 * NW + NFC + NB + NS;
    for (long i = (long)blockIdx.x * blockDim.x + threadIdx.x; i < total;
         i += (long)gridDim.x * blockDim.x) {
        long r = i;
        if (r < 2 * NW) {
            int ed = (int)(r / NW);
            long l = r % NW;
            int jh = (int)(l / (64L * H_));
            int rr = (int)((l / H_) % 64);
            int k  = (int)(l % H_);
            int g = rr >> 4, hh = rr & 15;
            long n = (long)g * H_ + jh * 16 + hh;
            const float* whh = ed ? dec_whh : enc_whh;
            g_W2[ed][l] = __float2half(whh[n * H_ + k]);
        } else if (r < 2 * NW + NFC) {
            long l = r - 2 * NW;
            g_fcw16[l] = __float2half(fc_w[l]);
        } else if (r < 2 * NW + NFC + NB) {
            long l = r - 2 * NW - NFC;
            g_biasfc[l] = fc_b[l % V_];
        } else {
            long l = r - 2 * NW - NFC - NB;
            g_hf[0][l] = __float2half(0.f);
        }
    }
}

// ---------------- persistent kernel: all 255 LSTM steps, 2 CTAs per SM ----------------
// CTA (bg, jh): batch rows bg*128..+127, h-dims jh*16..+15 (x4 gates = 64 gate rows).
// 8 warps: wk = warp>>2 splits K (256 each); wb = warp&3 tiles batch (32 each, 2 cb).
// acc[4][2] per warp; c state in wk=0 regs; asymmetric spill-safe epilogue (R13 proven).
// wk=0 warps do their OWN-rows h writeback after __syncwarp (same-warp STS->LDS), saving
// one CTA sync. Barrier spin is sleepless for minimal discovery latency.
__global__ __launch_bounds__(THREADS, 2) void seq_kernel(
    const int* __restrict__ src, const int* __restrict__ tgt)
{
    extern __shared__ __align__(16) char smem[];
    __half* Ws  = (__half*)smem;                        // [64 gate-row][LDH k] resident
    __half* hb0 = (__half*)(smem + W2BYTES);            // wk=0 chunk buffer
    __half* hb1 = (__half*)(smem + W2BYTES + CHUNKB);   // wk=1 chunk buffer
    float*  GS   = (float*)(smem + W2BYTES);            // [128 b][68 j] (aliases hb0/hb1)
    float*  hout = (float*)(smem + W2BYTES + GS2_B);    // [128 b][20 h]
    __shared__ int tok_s[128];

    const int tid  = threadIdx.x;
    const int warp = tid >> 5;
    const int lane = tid & 31;
    const int wk   = warp >> 2;         // K half
    const int wb   = warp & 3;          // batch sub-tile (32)
    const int jh   = blockIdx.x & 31;
    const int b0   = (blockIdx.x >> 5) * 128;
    const int btg  = blockIdx.x >> 5;   // barrier group (32 CTAs each)

    // resident encoder W tile (64 rows x 512 k)
    {
        const __half* __restrict__ W = g_W2[0] + (long)jh * 64 * H_;
        for (int i = tid; i < 64 * 64; i += THREADS) {
            int r = i >> 6, q = i & 63;
            cpa16(Ws + r * LDH + q * 8, W + (long)r * H_ + q * 8);
        }
        CPC(); CPW(0);
        __syncthreads();
    }

    // persistent cell state (wk=0 warps only): 16 h x 32 b per warp
    wmma::fragment<wmma::accumulator, 16, 16, 16, float> cfr[2];
    wmma::fill_fragment(cfr[0], 0.f);
    wmma::fill_fragment(cfr[1], 0.f);

    for (int st = 0; st < NSTEP; ++st) {
        const int is_dec = st >= S_;
        const int t   = is_dec ? st - S_ : st;
        const int par = st & 1;
        const int* __restrict__ tok = is_dec ? tgt : src;
        const __half* __restrict__ hg = g_hf[par];

        if (st == S_) {   // swap to decoder weights (CTA-local)
            const __half* __restrict__ W = g_W2[1] + (long)jh * 64 * H_;
            for (int i = tid; i < 64 * 64; i += THREADS) {
                int r = i >> 6, q = i & 63;
                cpa16(Ws + r * LDH + q * 8, W + (long)r * H_ + q * 8);
            }
            CPC(); CPW(0);
            __syncthreads();
        }

        if (tid < 128) tok_s[tid] = tok[(long)(b0 + tid) * 128 + t];

        // prologue: chunk 0 (wk0) and 4 (wk1)
        CPCH(hb0, 0); CPCH(hb1, 4); CPC();

        wmma::fragment<wmma::accumulator, 16, 16, 16, float> acc[4][2];
        #pragma unroll
        for (int g = 0; g < 4; g++) {
            wmma::fill_fragment(acc[g][0], 0.f);
            wmma::fill_fragment(acc[g][1], 0.f);
        }

        #pragma unroll 1
        for (int c = 0; c < 4; c++) {
            CPW(0);
            __syncthreads();
            const __half* cw = wk ? hb1 : hb0;
            const int ch = wk * 4 + c;           // this warp's K chunk
            #pragma unroll
            for (int kk = 0; kk < 4; kk++) {
                wmma::fragment<wmma::matrix_b, 16, 16, 16, half, wmma::col_major> bf[2];
                #pragma unroll
                for (int cb = 0; cb < 2; cb++)
                    wmma::load_matrix_sync(bf[cb], cw + (wb * 32 + cb * 16) * LDW + kk * 16, LDW);
                #pragma unroll
                for (int g = 0; g < 4; g++) {
                    wmma::fragment<wmma::matrix_a, 16, 16, 16, half, wmma::row_major> af;
                    wmma::load_matrix_sync(af, Ws + (g * 16) * LDH + ch * 64 + kk * 16, LDH);
                    wmma::mma_sync(acc[g][0], af, bf[0], acc[g][0]);
                    wmma::mma_sync(acc[g][1], af, bf[1], acc[g][1]);
                }
            }
            __syncthreads();                     // all warps done reading buffers
            if (c < 3) {
                CPCH(hb0, c + 1);
                CPCH(hb1, c + 5);
                CPC();
            }
        }

        // -------- epilogue (asymmetric, spill-safe: wk=1 stores, wk=0 finalizes) --------
        if (wk == 1) {
            #pragma unroll
            for (int g = 0; g < 4; g++)
                #pragma unroll
                for (int cb = 0; cb < 2; cb++)
                    wmma::store_matrix_sync(GS + (wb * 32 + cb * 16) * 68 + g * 16,
                                            acc[g][cb], 68, wmma::mem_col_major);
        }
        __syncthreads();

        // all threads: GS += embproj gather (float4; 16 f4 per batch row)
        const float* __restrict__ EP = g_embp[is_dec];
        #pragma unroll
        for (int it = 0; it < 8; it++) {
            int i = tid + it * THREADS;          // 2048 total
            int b = i >> 4, f = i & 15;
            int g = f >> 2, q = f & 3;
            const float4 ev = *reinterpret_cast<const float4*>(
                &EP[(long)tok_s[b] * G4 + (long)g * H_ + jh * 16 + q * 4]);
            float* gp = &GS[b * 68 + g * 16 + q * 4];
            float4 gv = *reinterpret_cast<float4*>(gp);
            gv.x += ev.x; gv.y += ev.y; gv.z += ev.z; gv.w += ev.w;
            *reinterpret_cast<float4*>(gp) = gv;
        }
        __syncthreads();

        // wk=0 warps: combine + cell update (c in registers), stage h, and write back
        // THEIR OWN rows (same-warp STS->LDS; only __syncwarp needed, no CTA sync).
        __half* __restrict__ hg2 = g_hf[par ^ 1];
        if (wk == 0) {
            #pragma unroll
            for (int cb = 0; cb < 2; cb++) {
                const int bl = wb * 32 + cb * 16;
                wmma::fragment<wmma::accumulator, 16, 16, 16, float> xf, hn;
                #pragma unroll
                for (int g = 0; g < 4; g++) {
                    wmma::load_matrix_sync(xf, GS + bl * 68 + g * 16, 68, wmma::mem_col_major);
                    #pragma unroll
                    for (int e = 0; e < 8; e++) acc[g][cb].x[e] += xf.x[e];
                }
                #pragma unroll
                for (int e = 0; e < 8; e++) {
                    float ig = sigm(acc[0][cb].x[e]);
                    float fg = sigm(acc[1][cb].x[e]);
                    float gg = tanhfast(acc[2][cb].x[e]);
                    float og = sigm(acc[3][cb].x[e]);
                    float c2 = fg * cfr[cb].x[e] + ig * gg;
                    cfr[cb].x[e] = c2;
                    hn.x[e] = og * tanhfast(c2);
                }
                wmma::store_matrix_sync(hout + bl * 20, hn, 20, wmma::mem_col_major);
            }
            __syncwarp();
            // write back this warp's 32 b-rows (bl0 = wb*32 .. +31): 4 uint2 per lane
            const int blw = wb * 32;
            #pragma unroll
            for (int it = 0; it < 4; it++) {
                int i = lane + it * 32;          // 128 per warp
                int b = blw + (i >> 2), q = i & 3;
                float4 hv = *reinterpret_cast<const float4*>(&hout[b * 20 + q * 4]);
                __half2 h2a = __floats2half2_rn(hv.x, hv.y);
                __half2 h2b = __floats2half2_rn(hv.z, hv.w);
                uint2 o = make_uint2(*reinterpret_cast<uint32_t*>(&h2a),
                                     *reinterpret_cast<uint32_t*>(&h2b));
                *reinterpret_cast<uint2*>(&hg2[(long)(b0 + b) * H_ + jh * 16 + q * 4]) = o;
                if (is_dec)
                    *reinterpret_cast<uint2*>(
                        &g_hseq[((long)(b0 + b) * (T_ - 1) + t) * H_ + jh * 16 + q * 4]) = o;
            }
        }

        // -------- per-b-group barrier (32 CTAs), tid0-only cumulative fence --------
        if (st + 1 < NSTEP) {
            __syncthreads();                       // covers wk=0 STGs for the fence
            if (tid == 0) {
                __threadfence();                   // cumulative after syncthreads
                atomicAdd(&g_bar8[btg * 32], 1u);
                const unsigned target = (unsigned)(st + 1) * 32u;
                while (*(volatile unsigned*)&g_bar8[btg * 32] < target) { }
            }
            __syncthreads();
        }
    }
}

// ---------------- FC head: logits = h_seq @ fc_w^T + fc_b (fp16 in, fp32 acc) ----------
__global__ __launch_bounds__(256, 1) void fc_kernel()
{
    extern __shared__ __align__(16) char smem[];
    __half* bsm = (__half*)smem;
    __half* ab0 = (__half*)(smem + 128 * LDH * 2);
    __half* ab1 = (__half*)(smem + 128 * LDH * 2 + 128 * LDW * 2);

    const int tid = threadIdx.x;
    const int warp = tid >> 5;
    const int wm = warp >> 2;
    const int wn = warp & 3;
    const long m0 = (long)blockIdx.x * 128;

    for (int i = tid; i < 128 * 64; i += 256) {
        int r = i >> 6, q = i & 63;
        cpa16(bsm + r * LDH + q * 8, g_fcw16 + (long)r * H_ + q * 8);
    }
    for (int i = tid; i < 128 * 8; i += 256) {
        int r = i >> 3, q = i & 7;
        cpa16(ab0 + r * LDW + q * 8, g_hseq + (m0 + r) * H_ + q * 8);
    }
    CPC();
    for (int i = tid; i < 128 * 8; i += 256) {
        int r = i >> 3, q = i & 7;
        cpa16(ab1 + r * LDW + q * 8, g_hseq + (m0 + r) * H_ + 64 + q * 8);
    }
    CPC();
    CPW(1);
    __syncthreads();

    wmma::fragment<wmma::accumulator, 16, 16, 16, float> acc[4][2];
    #pragma unroll
    for (int mm = 0; mm < 4; mm++)
        #pragma unroll
        for (int cb = 0; cb < 2; cb++)
            wmma::load_matrix_sync(acc[mm][cb], g_biasfc + wn * 32 + cb * 16, V_, wmma::mem_row_major);

    #pragma unroll 1
    for (int ch = 0; ch < 8; ch++) {
        const __half* ca = (ch & 1) ? ab1 : ab0;
        #pragma unroll
        for (int kk = 0; kk < 4; kk++) {
            wmma::fragment<wmma::matrix_b, 16, 16, 16, half, wmma::col_major> bf[2];
            #pragma unroll
            for (int cb = 0; cb < 2; cb++)
                wmma::load_matrix_sync(bf[cb], bsm + (wn * 32 + cb * 16) * LDH + ch * 64 + kk * 16, LDH);
            #pragma unroll
            for (int mm = 0; mm < 4; mm++) {
                wmma::fragment<wmma::matrix_a, 16, 16, 16, half, wmma::row_major> af;
                wmma::load_matrix_sync(af, ca + (wm * 64 + mm * 16) * LDW + kk * 16, LDW);
                wmma::mma_sync(acc[mm][0], af, bf[0], acc[mm][0]);
                wmma::mma_sync(acc[mm][1], af, bf[1], acc[mm][1]);
            }
        }
        __syncthreads();
        if (ch + 2 < 8) {
            __half* nb = (ch & 1) ? ab1 : ab0;
            for (int i = tid; i < 128 * 8; i += 256) {
                int r = i >> 3, q = i & 7;
                cpa16(nb + r * LDW + q * 8, g_hseq + (m0 + r) * H_ + (ch + 2) * 64 + q * 8);
            }
            CPC();
        }
        if (ch + 1 < 8) {
            if (ch + 2 < 8) { CPW(1); } else { CPW(0); }
            __syncthreads();
        }
    }

    #pragma unroll
    for (int mm = 0; mm < 4; mm++)
        #pragma unroll
        for (int cb = 0; cb < 2; cb++)
            wmma::store_matrix_sync(g_logits + (m0 + wm * 64 + mm * 16) * V_ + wn * 32 + cb * 16,
                                    acc[mm][cb], V_, wmma::mem_row_major);
}

// ---------------- scatter logits into (B, T, V) with zero row at t=0 ----------------
__global__ void out_kernel(float* __restrict__ out)
{
    const long n4 = (long)B_ * T_ * V_ / 4;
    for (long i = (long)blockIdx.x * blockDim.x + threadIdx.x; i < n4;
         i += (long)gridDim.x * blockDim.x) {
        long e = i * 4;
        int  v  = (int)(e % V_);
        long bt = e / V_;
        int  tt = (int)(bt % T_);
        long b  = bt / T_;
        float4 val;
        if (tt == 0) val = make_float4(0.f, 0.f, 0.f, 0.f);
        else val = *reinterpret_cast<const float4*>(
                       &g_logits[(b * (T_ - 1) + (tt - 1)) * V_ + v]);
        reinterpret_cast<float4*>(out)[i] = val;
    }
}

// ---------------- launch ----------------
extern "C" void kernel_launch(void* const* d_in, const int* in_sizes, int n_in,
                              void* d_out, int out_size)
{
    (void)in_sizes; (void)n_in; (void)out_size;
    const int*   src      = (const int*)  d_in[0];
    const int*   target   = (const int*)  d_in[1];
    const float* emb      = (const float*)d_in[2];
    const float* dec_emb  = (const float*)d_in[3];
    const float* enc_wih  = (const float*)d_in[4];
    const float* enc_whh  = (const float*)d_in[5];
    const float* enc_bih  = (const float*)d_in[6];
    const float* enc_bhh  = (const float*)d_in[7];
    const float* dec_wih  = (const float*)d_in[8];
    const float* dec_whh  = (const float*)d_in[9];
    const float* dec_bih  = (const float*)d_in[10];
    const float* dec_bhh  = (const float*)d_in[11];
    const float* fc_w     = (const float*)d_in[12];
    const float* fc_b     = (const float*)d_in[13];
    float* out = (float*)d_out;

    cudaFuncSetAttribute(seq_kernel, cudaFuncAttributeMaxDynamicSharedMemorySize, SEQ_SMEM);
    cudaFuncSetAttribute(fc_kernel,  cudaFuncAttributeMaxDynamicSharedMemorySize, FC_SMEM);

    prep_embproj<<<dim3(V_, G4 / 256), 256>>>(emb,     enc_wih, enc_bih, enc_bhh, 0);
    prep_embproj<<<dim3(V_, G4 / 256), 256>>>(dec_emb, dec_wih, dec_bih, dec_bhh, 1);
    prep2<<<2048, 256>>>(enc_whh, dec_whh, fc_w, fc_b);

    seq_kernel<<<NCTA, THREADS, SEQ_SMEM>>>(src, target);

    fc_kernel<<<(B_ * (T_ - 1)) / 128, 256, FC_SMEM>>>();
    out_kernel<<<2048, 256>>>(out);
}

// round 17
// speedup vs baseline: 1.5159x; 1.0095x over previous
#include <cuda_runtime.h>
#include <cuda_fp16.h>
#include <mma.h>
#include <cstdint>

using namespace nvcuda;

#define B_   1024
#define H_   512
#define E_   256
#define S_   128
#define T_   128
#define V_   128
#define G4   2048
#define NCTA 256                 // 32 j-tiles x 8 b-groups
#define NSTEP (S_ + T_ - 1)      // 255
#define THREADS 256
#define LDH  520                 // smem ld (halves) for resident W rows
#define LDW  72                  // smem ld (halves) for streamed h chunks
#define CHUNKB (128 * LDW * 2)   // 18432 bytes per 64-k chunk
#define W2BYTES (64 * LDH * 2)   // 66560: resident W tile (64 gate-rows)
#define GS2_B  (128 * 68 * 4)    // 34816: gate staging fp32 [128 b][68 j]
#define HO2_B  (128 * 20 * 4)    // 10240: hout fp32 [128 b][20 h]
#define SEQ_SMEM (W2BYTES + GS2_B + HO2_B)            // 111616 -> 2 CTAs/SM
#define FC_SMEM  (128 * LDH * 2 + 2 * 128 * LDW * 2)  // 169984

// ---------------- device scratch ----------------
__device__ __half g_W2[2][32 * 64 * H_];             // reordered whh fp16: [jh][gate*16+r][k]
__device__ float  g_embp[2][(long)V_ * G4];          // emb @ wih^T + bih + bhh (exact fp32)
__device__ __half g_fcw16[V_ * H_];
__device__ float  g_biasfc[16 * V_];
__device__ __half g_hf[2][(long)B_ * H_];            // hidden fp16, double buffered (cross-CTA via L2)
__device__ __half g_hseq[(long)B_ * T_ * H_];        // [b][T][h]; decoder writes slot t+1; row 0 unused
__device__ unsigned g_bar8[8 * 32];                  // per-b-group barrier counters (128B apart)

// fast activations: MUFU-based, rel err ~1e-6 (validated R7-R16)
__device__ __forceinline__ float sigm(float x) {
    return __fdividef(1.f, 1.f + __expf(-x));
}
__device__ __forceinline__ float tanhfast(float x) {
    float s = __fdividef(1.f, 1.f + __expf(-2.f * x));
    return fmaf(2.f, s, -1.f);
}

__device__ __forceinline__ void cpa16(void* dst, const void* src) {
    unsigned d = (unsigned)__cvta_generic_to_shared(dst);
    asm volatile("cp.async.cg.shared.global [%0], [%1], 16;\n" :: "r"(d), "l"(src));
}
#define CPC()  asm volatile("cp.async.commit_group;\n" ::: "memory")
#define CPW(n) asm volatile("cp.async.wait_group %0;\n" :: "n"(n) : "memory")

// copy 64-k chunk ch of this CTA's h tile into smem buffer (all 256 threads, 4 ops each)
#define CPCH(buf, ch)                                                             \
    _Pragma("unroll")                                                             \
    for (int it_ = 0; it_ < 4; it_++) {                                           \
        int i_ = threadIdx.x + it_ * THREADS;                                     \
        int r_ = i_ >> 3, q_ = i_ & 7;                                            \
        cpa16((buf) + r_ * LDW + q_ * 8, hg + (long)(b0 + r_) * H_ + (ch) * 64 + q_ * 8); \
    }

// ---------------- prep A: embproj = emb @ wih^T + bih + bhh (exact fp32), both dirs ------
__global__ void prep_embproj(const float* __restrict__ emb0, const float* __restrict__ wih0,
                             const float* __restrict__ bih0, const float* __restrict__ bhh0,
                             const float* __restrict__ emb1, const float* __restrict__ wih1,
                             const float* __restrict__ bih1, const float* __restrict__ bhh1)
{
    const int is_dec = blockIdx.z;
    const float* __restrict__ emb = is_dec ? emb1 : emb0;
    const float* __restrict__ wih = is_dec ? wih1 : wih0;
    const float* __restrict__ bih = is_dec ? bih1 : bih0;
    const float* __restrict__ bhh = is_dec ? bhh1 : bhh0;
    __shared__ float er[E_];
    int v = blockIdx.x;
    int n = blockIdx.y * 256 + threadIdx.x;
    er[threadIdx.x] = emb[(long)v * E_ + threadIdx.x];
    __syncthreads();
    float s = bih[n] + bhh[n];
    const float* wr = wih + (long)n * E_;
    #pragma unroll 8
    for (int k = 0; k < E_; k++) s += er[k] * wr[k];
    g_embp[is_dec][(long)v * G4 + n] = s;
}

// ---------------- prep B: reorder whh fp16 (32 j-tiles of 16h x 4 gates), fc, h0, bars ---
__global__ void prep2(const float* __restrict__ enc_whh, const float* __restrict__ dec_whh,
                      const float* __restrict__ fc_w,    const float* __restrict__ fc_b)
{
    if (blockIdx.x == 0 && threadIdx.x < 8 * 32) g_bar8[threadIdx.x] = 0u;
    const long NW  = 32L * 64 * H_;
    const long NFC = (long)V_ * H_;
    const long NB  = 16L * V_;
    const long NS  = (long)B_ * H_;
    const long total = 2 * NW + NFC + NB + NS;
    for (long i = (long)blockIdx.x * blockDim.x + threadIdx.x; i < total;
         i += (long)gridDim.x * blockDim.x) {
        long r = i;
        if (r < 2 * NW) {
            int ed = (int)(r / NW);
            long l = r % NW;
            int jh = (int)(l / (64L * H_));
            int rr = (int)((l / H_) % 64);
            int k  = (int)(l % H_);
            int g = rr >> 4, hh = rr & 15;
            long n = (long)g * H_ + jh * 16 + hh;
            const float* whh = ed ? dec_whh : enc_whh;
            g_W2[ed][l] = __float2half(whh[n * H_ + k]);
        } else if (r < 2 * NW + NFC) {
            long l = r - 2 * NW;
            g_fcw16[l] = __float2half(fc_w[l]);
        } else if (r < 2 * NW + NFC + NB) {
            long l = r - 2 * NW - NFC;
            g_biasfc[l] = fc_b[l % V_];
        } else {
            long l = r - 2 * NW - NFC - NB;
            g_hf[0][l] = __float2half(0.f);
        }
    }
}

// ---------------- persistent kernel: all 255 LSTM steps, 2 CTAs per SM ----------------
// CTA (bg, jh): batch rows bg*128..+127, h-dims jh*16..+15 (x4 gates = 64 gate rows).
// 8 warps: wk = warp>>2 splits K (256 each); wb = warp&3 tiles batch (32 each, 2 cb).
// acc[4][2] per warp; c state in wk=0 regs; asymmetric spill-safe epilogue (R13 proven).
// wk=0 warps do their own-rows h writeback after __syncwarp. Decoder h -> g_hseq slot t+1.
__global__ __launch_bounds__(THREADS, 2) void seq_kernel(
    const int* __restrict__ src, const int* __restrict__ tgt)
{
    extern __shared__ __align__(16) char smem[];
    __half* Ws  = (__half*)smem;                        // [64 gate-row][LDH k] resident
    __half* hb0 = (__half*)(smem + W2BYTES);            // wk=0 chunk buffer
    __half* hb1 = (__half*)(smem + W2BYTES + CHUNKB);   // wk=1 chunk buffer
    float*  GS   = (float*)(smem + W2BYTES);            // [128 b][68 j] (aliases hb0/hb1)
    float*  hout = (float*)(smem + W2BYTES + GS2_B);    // [128 b][20 h]
    __shared__ int tok_s[128];

    const int tid  = threadIdx.x;
    const int warp = tid >> 5;
    const int lane = tid & 31;
    const int wk   = warp >> 2;         // K half
    const int wb   = warp & 3;          // batch sub-tile (32)
    const int jh   = blockIdx.x & 31;
    const int b0   = (blockIdx.x >> 5) * 128;
    const int btg  = blockIdx.x >> 5;   // barrier group (32 CTAs each)

    // resident encoder W tile (64 rows x 512 k)
    {
        const __half* __restrict__ W = g_W2[0] + (long)jh * 64 * H_;
        for (int i = tid; i < 64 * 64; i += THREADS) {
            int r = i >> 6, q = i & 63;
            cpa16(Ws + r * LDH + q * 8, W + (long)r * H_ + q * 8);
        }
        CPC(); CPW(0);
        __syncthreads();
    }

    // persistent cell state (wk=0 warps only): 16 h x 32 b per warp
    wmma::fragment<wmma::accumulator, 16, 16, 16, float> cfr[2];
    wmma::fill_fragment(cfr[0], 0.f);
    wmma::fill_fragment(cfr[1], 0.f);

    for (int st = 0; st < NSTEP; ++st) {
        const int is_dec = st >= S_;
        const int t   = is_dec ? st - S_ : st;
        const int par = st & 1;
        const int* __restrict__ tok = is_dec ? tgt : src;
        const __half* __restrict__ hg = g_hf[par];

        if (st == S_) {   // swap to decoder weights (CTA-local)
            const __half* __restrict__ W = g_W2[1] + (long)jh * 64 * H_;
            for (int i = tid; i < 64 * 64; i += THREADS) {
                int r = i >> 6, q = i & 63;
                cpa16(Ws + r * LDH + q * 8, W + (long)r * H_ + q * 8);
            }
            CPC(); CPW(0);
            __syncthreads();
        }

        if (tid < 128) tok_s[tid] = tok[(long)(b0 + tid) * 128 + t];

        // prologue: chunk 0 (wk0) and 4 (wk1)
        CPCH(hb0, 0); CPCH(hb1, 4); CPC();

        wmma::fragment<wmma::accumulator, 16, 16, 16, float> acc[4][2];
        #pragma unroll
        for (int g = 0; g < 4; g++) {
            wmma::fill_fragment(acc[g][0], 0.f);
            wmma::fill_fragment(acc[g][1], 0.f);
        }

        #pragma unroll 1
        for (int c = 0; c < 4; c++) {
            CPW(0);
            __syncthreads();
            const __half* cw = wk ? hb1 : hb0;
            const int ch = wk * 4 + c;           // this warp's K chunk
            #pragma unroll
            for (int kk = 0; kk < 4; kk++) {
                wmma::fragment<wmma::matrix_b, 16, 16, 16, half, wmma::col_major> bf[2];
                #pragma unroll
                for (int cb = 0; cb < 2; cb++)
                    wmma::load_matrix_sync(bf[cb], cw + (wb * 32 + cb * 16) * LDW + kk * 16, LDW);
                #pragma unroll
                for (int g = 0; g < 4; g++) {
                    wmma::fragment<wmma::matrix_a, 16, 16, 16, half, wmma::row_major> af;
                    wmma::load_matrix_sync(af, Ws + (g * 16) * LDH + ch * 64 + kk * 16, LDH);
                    wmma::mma_sync(acc[g][0], af, bf[0], acc[g][0]);
                    wmma::mma_sync(acc[g][1], af, bf[1], acc[g][1]);
                }
            }
            __syncthreads();                     // all warps done reading buffers
            if (c < 3) {
                CPCH(hb0, c + 1);
                CPCH(hb1, c + 5);
                CPC();
            }
        }

        // -------- epilogue (asymmetric, spill-safe: wk=1 stores, wk=0 finalizes) --------
        if (wk == 1) {
            #pragma unroll
            for (int g = 0; g < 4; g++)
                #pragma unroll
                for (int cb = 0; cb < 2; cb++)
                    wmma::store_matrix_sync(GS + (wb * 32 + cb * 16) * 68 + g * 16,
                                            acc[g][cb], 68, wmma::mem_col_major);
        }
        __syncthreads();

        // all threads: GS += embproj gather (float4; 16 f4 per batch row)
        const float* __restrict__ EP = g_embp[is_dec];
        #pragma unroll
        for (int it = 0; it < 8; it++) {
            int i = tid + it * THREADS;          // 2048 total
            int b = i >> 4, f = i & 15;
            int g = f >> 2, q = f & 3;
            const float4 ev = *reinterpret_cast<const float4*>(
                &EP[(long)tok_s[b] * G4 + (long)g * H_ + jh * 16 + q * 4]);
            float* gp = &GS[b * 68 + g * 16 + q * 4];
            float4 gv = *reinterpret_cast<float4*>(gp);
            gv.x += ev.x; gv.y += ev.y; gv.z += ev.z; gv.w += ev.w;
            *reinterpret_cast<float4*>(gp) = gv;
        }
        __syncthreads();

        // wk=0 warps: combine + cell update (c in registers), stage h, write own rows back
        __half* __restrict__ hg2 = g_hf[par ^ 1];
        if (wk == 0) {
            #pragma unroll
            for (int cb = 0; cb < 2; cb++) {
                const int bl = wb * 32 + cb * 16;
                wmma::fragment<wmma::accumulator, 16, 16, 16, float> xf, hn;
                #pragma unroll
                for (int g = 0; g < 4; g++) {
                    wmma::load_matrix_sync(xf, GS + bl * 68 + g * 16, 68, wmma::mem_col_major);
                    #pragma unroll
                    for (int e = 0; e < 8; e++) acc[g][cb].x[e] += xf.x[e];
                }
                #pragma unroll
                for (int e = 0; e < 8; e++) {
                    float ig = sigm(acc[0][cb].x[e]);
                    float fg = sigm(acc[1][cb].x[e]);
                    float gg = tanhfast(acc[2][cb].x[e]);
                    float og = sigm(acc[3][cb].x[e]);
                    float c2 = fg * cfr[cb].x[e] + ig * gg;
                    cfr[cb].x[e] = c2;
                    hn.x[e] = og * tanhfast(c2);
                }
                wmma::store_matrix_sync(hout + bl * 20, hn, 20, wmma::mem_col_major);
            }
            __syncwarp();
            // write back this warp's 32 b-rows: 4 uint2 per lane
            const int blw = wb * 32;
            #pragma unroll
            for (int it = 0; it < 4; it++) {
                int i = lane + it * 32;          // 128 per warp
                int b = blw + (i >> 2), q = i & 3;
                float4 hv = *reinterpret_cast<const float4*>(&hout[b * 20 + q * 4]);
                __half2 h2a = __floats2half2_rn(hv.x, hv.y);
                __half2 h2b = __floats2half2_rn(hv.z, hv.w);
                uint2 o = make_uint2(*reinterpret_cast<uint32_t*>(&h2a),
                                     *reinterpret_cast<uint32_t*>(&h2b));
                *reinterpret_cast<uint2*>(&hg2[(long)(b0 + b) * H_ + jh * 16 + q * 4]) = o;
                if (is_dec)   // slot t+1 in [b][T][h] layout (row 0 stays unused)
                    *reinterpret_cast<uint2*>(
                        &g_hseq[((long)(b0 + b) * T_ + (t + 1)) * H_ + jh * 16 + q * 4]) = o;
            }
        }

        // -------- per-b-group barrier (32 CTAs), tid0-only cumulative fence --------
        if (st + 1 < NSTEP) {
            __syncthreads();                       // covers wk=0 STGs for the fence
            if (tid == 0) {
                __threadfence();                   // cumulative after syncthreads
                atomicAdd(&g_bar8[btg * 32], 1u);
                const unsigned target = (unsigned)(st + 1) * 32u;
                while (*(volatile unsigned*)&g_bar8[btg * 32] < target) { }
            }
            __syncthreads();
        }
    }
}

// ---------------- FC head fused with output scatter ----------------
// grid = B (one CTA per b, 128 rows = t 0..127). Reads g_hseq [b][T][h] (row 0 garbage),
// writes logits DIRECTLY to out[b][t][v]; after a sync, row t=0 is overwritten with zeros.
__global__ __launch_bounds__(256, 1) void fc_kernel(float* __restrict__ out)
{
    extern __shared__ __align__(16) char smem[];
    __half* bsm = (__half*)smem;
    __half* ab0 = (__half*)(smem + 128 * LDH * 2);
    __half* ab1 = (__half*)(smem + 128 * LDH * 2 + 128 * LDW * 2);

    const int tid = threadIdx.x;
    const int warp = tid >> 5;
    const int wm = warp >> 2;
    const int wn = warp & 3;
    const long m0 = (long)blockIdx.x * 128;      // = b * T

    for (int i = tid; i < 128 * 64; i += 256) {
        int r = i >> 6, q = i & 63;
        cpa16(bsm + r * LDH + q * 8, g_fcw16 + (long)r * H_ + q * 8);
    }
    for (int i = tid; i < 128 * 8; i += 256) {
        int r = i >> 3, q = i & 7;
        cpa16(ab0 + r * LDW + q * 8, g_hseq + (m0 + r) * H_ + q * 8);
    }
    CPC();
    for (int i = tid; i < 128 * 8; i += 256) {
        int r = i >> 3, q = i & 7;
        cpa16(ab1 + r * LDW + q * 8, g_hseq + (m0 + r) * H_ + 64 + q * 8);
    }
    CPC();
    CPW(1);
    __syncthreads();

    wmma::fragment<wmma::accumulator, 16, 16, 16, float> acc[4][2];
    #pragma unroll
    for (int mm = 0; mm < 4; mm++)
        #pragma unroll
        for (int cb = 0; cb < 2; cb++)
            wmma::load_matrix_sync(acc[mm][cb], g_biasfc + wn * 32 + cb * 16, V_, wmma::mem_row_major);

    #pragma unroll 1
    for (int ch = 0; ch < 8; ch++) {
        const __half* ca = (ch & 1) ? ab1 : ab0;
        #pragma unroll
        for (int kk = 0; kk < 4; kk++) {
            wmma::fragment<wmma::matrix_b, 16, 16, 16, half, wmma::col_major> bf[2];
            #pragma unroll
            for (int cb = 0; cb < 2; cb++)
                wmma::load_matrix_sync(bf[cb], bsm + (wn * 32 + cb * 16) * LDH + ch * 64 + kk * 16, LDH);
            #pragma unroll
            for (int mm = 0; mm < 4; mm++) {
                wmma::fragment<wmma::matrix_a, 16, 16, 16, half, wmma::row_major> af;
                wmma::load_matrix_sync(af, ca + (wm * 64 + mm * 16) * LDW + kk * 16, LDW);
                wmma::mma_sync(acc[mm][0], af, bf[0], acc[mm][0]);
                wmma::mma_sync(acc[mm][1], af, bf[1], acc[mm][1]);
            }
        }
        __syncthreads();
        if (ch + 2 < 8) {
            __half* nb = (ch & 1) ? ab1 : ab0;
            for (int i = tid; i < 128 * 8; i += 256) {
                int r = i >> 3, q = i & 7;
                cpa16(nb + r * LDW + q * 8, g_hseq + (m0 + r) * H_ + (ch + 2) * 64 + q * 8);
            }
            CPC();
        }
        if (ch + 1 < 8) {
            if (ch + 2 < 8) { CPW(1); } else { CPW(0); }
            __syncthreads();
        }
    }

    #pragma unroll
    for (int mm = 0; mm < 4; mm++)
        #pragma unroll
        for (int cb = 0; cb < 2; cb++)
            wmma::store_matrix_sync(out + (m0 + wm * 64 + mm * 16) * V_ + wn * 32 + cb * 16,
                                    acc[mm][cb], V_, wmma::mem_row_major);

    // zero the t=0 row of this b (overwrites the garbage-h logits row)
    __syncthreads();
    if (tid < 32)
        reinterpret_cast<float4*>(out + m0 * V_)[tid] = make_float4(0.f, 0.f, 0.f, 0.f);
}

// ---------------- launch ----------------
extern "C" void kernel_launch(void* const* d_in, const int* in_sizes, int n_in,
                              void* d_out, int out_size)
{
    (void)in_sizes; (void)n_in; (void)out_size;
    const int*   src      = (const int*)  d_in[0];
    const int*   target   = (const int*)  d_in[1];
    const float* emb      = (const float*)d_in[2];
    const float* dec_emb  = (const float*)d_in[3];
    const float* enc_wih  = (const float*)d_in[4];
    const float* enc_whh  = (const float*)d_in[5];
    const float* enc_bih  = (const float*)d_in[6];
    const float* enc_bhh  = (const float*)d_in[7];
    const float* dec_wih  = (const float*)d_in[8];
    const float* dec_whh  = (const float*)d_in[9];
    const float* dec_bih  = (const float*)d_in[10];
    const float* dec_bhh  = (const float*)d_in[11];
    const float* fc_w     = (const float*)d_in[12];
    const float* fc_b     = (const float*)d_in[13];
    float* out = (float*)d_out;

    cudaFuncSetAttribute(seq_kernel, cudaFuncAttributeMaxDynamicSharedMemorySize, SEQ_SMEM);
    cudaFuncSetAttribute(fc_kernel,  cudaFuncAttributeMaxDynamicSharedMemorySize, FC_SMEM);

    prep_embproj<<<dim3(V_, G4 / 256, 2), 256>>>(emb, enc_wih, enc_bih, enc_bhh,
                                                 dec_emb, dec_wih, dec_bih, dec_bhh);
    prep2<<<2048, 256>>>(enc_whh, dec_whh, fc_w, fc_b);

    seq_kernel<<<NCTA, THREADS, SEQ_SMEM>>>(src, target);

    fc_kernel<<<B_, 256, FC_SMEM>>>(out);
}